// round 10
// baseline (speedup 1.0000x reference)
#include <cuda_runtime.h>
#include <cuda_fp16.h>
#include <cstdint>
#include <math.h>

#define DEVFN static __device__ __forceinline__

// ---------------- problem constants ----------------
constexpr int NN = 12000;
constexpr int FF = 256;
constexpr float SCALE1     = 16384.f;    // pre-scale on `scaled` (GEMM1 B)
constexpr float INV_SCALE1 = 1.f / 16384.f;

// ---------------- GEMM config ----------------
constexpr int BM = 128;
constexpr int BN = 256;
constexpr int SPLITK = 3;

constexpr int BK2 = 32;
constexpr int STAGES2 = 4;
constexpr int PADA2 = 40;                         // 16-bit elems per A row (80 B)
constexpr int PADB2 = 40;                         // 16-bit elems per B row (80 B)
constexpr int A_BYTES2 = BM * PADA2 * 2;          // 10240
constexpr int B_BYTES2 = BN * PADB2 * 2;          // 20480
constexpr int STAGE_BYTES2 = A_BYTES2 + B_BYTES2; // 30720
constexpr int DYN_SMEM2 = STAGES2 * STAGE_BYTES2; // 122880
constexpr int KCH_BIG2 = (NN / SPLITK) / BK2;     // 125

// ---------------- device scratch -------------------
__device__ float g_scores[NN];
__device__ float g_p[NN];
__device__ __half g_scaledT16[(size_t)FF * NN];   // B for GEMM1 (fp16, x2^14)
__device__ __half g_supportT16[(size_t)FF * NN];  // B for GEMM3 (fp16)
__device__ __half g_weightT16[FF * FF];           // B for GEMM2 (fp16)
__device__ __half g_support4h[(size_t)NN * FF];   // A for GEMM2 (fp16, row-major)
__device__ float g_part[(size_t)SPLITK * NN * FF];  // split-K partials
__device__ int g_cnt1[128];                       // split-K arrival counters
__device__ int g_cnt3[128];

// ---------------- PTX helpers ----------------------
DEVFN uint32_t smem_u32(const void* p) {
    uint32_t a;
    asm("{ .reg .u64 t; cvta.to.shared.u64 t, %1; cvt.u32.u64 %0, t; }" : "=r"(a) : "l"(p));
    return a;
}
DEVFN void cp_async16(uint32_t saddr, const void* gaddr) {
    asm volatile("cp.async.cg.shared.global [%0], [%1], 16;"
                 :: "r"(saddr), "l"(gaddr) : "memory");
}
DEVFN void cp_commit() { asm volatile("cp.async.commit_group;" ::: "memory"); }
template <int N> DEVFN void cp_wait() { asm volatile("cp.async.wait_group %0;" :: "n"(N) : "memory"); }

DEVFN void ldmatrix_x4(uint32_t& r0, uint32_t& r1, uint32_t& r2, uint32_t& r3,
                       uint32_t addr) {
    asm volatile("ldmatrix.sync.aligned.m8n8.x4.shared.b16 {%0,%1,%2,%3}, [%4];"
                 : "=r"(r0), "=r"(r1), "=r"(r2), "=r"(r3) : "r"(addr));
}
DEVFN uint32_t pack_h2(float lo, float hi) {
    __half2 h = __float22half2_rn(make_float2(lo, hi));
    return *reinterpret_cast<uint32_t*>(&h);
}
DEVFN void mma_fp16(float* c, const uint32_t* a, const uint32_t* b) {
    asm volatile(
        "mma.sync.aligned.m16n8k16.row.col.f32.f16.f16.f32 "
        "{%0,%1,%2,%3}, {%4,%5,%6,%7}, {%8,%9}, {%0,%1,%2,%3};"
        : "+f"(c[0]), "+f"(c[1]), "+f"(c[2]), "+f"(c[3])
        : "r"(a[0]), "r"(a[1]), "r"(a[2]), "r"(a[3]), "r"(b[0]), "r"(b[1]));
}

// ========================================================================
// Big GEMM with fused deterministic split-K reduction in the last block.
//   MODE 1 (GEMM1): last block writes support4h = fp16((Σp)*2^-14 + alpha*x)
//   MODE 3 (GEMM3): last block writes out fp32 = Σp
// All SPLITK blocks write fp32 partials; the last arrival re-reads all
// three slabs in fixed index order -> bitwise-deterministic result.
// ========================================================================
template <int MODE>
__global__ void __launch_bounds__(512, 1)
gemm_big(const float* __restrict__ A, int lda,
         const __half* __restrict__ B16, int ldb,
         int M, int kChunks,
         float* __restrict__ P,
         const float* __restrict__ inp,
         const float* __restrict__ alphaPtr,
         float* __restrict__ outp) {
    extern __shared__ char sm2[];

    const int tid  = threadIdx.x;
    const int wid  = tid >> 5;
    const int lane = tid & 31;
    const int l4   = lane >> 2;
    const int lm   = lane & 3;
    const int m0   = blockIdx.x * BM;
    const int wm   = (wid >> 2) * 32;
    const int wn   = (wid & 3) * 64;
    const size_t kStart = (size_t)blockIdx.y * kChunks * BK2;
    float* __restrict__ Pp = P + (size_t)blockIdx.y * NN * FF;

    const int q = lane >> 3;
    const int rr = lane & 7;
    const uint32_t boff_lane =
        (uint32_t)((wn + (q >> 1) * 8 + rr) * PADB2 * 2 + (q & 1) * 16);
    const uint32_t aoff_lane =
        (uint32_t)((wm + (lane & 15)) * PADA2 * 2 + (lane >> 4) * 16);

    const int arow = tid >> 2;
    const int aseg = tid & 3;
    const bool arow_ok = (m0 + arow) < M;
    const float* gArow = A + (size_t)(m0 + arow) * lda + kStart + aseg * 8;

    float acc[2][8][4];
#pragma unroll
    for (int mt = 0; mt < 2; ++mt)
#pragma unroll
        for (int nt = 0; nt < 8; ++nt)
#pragma unroll
            for (int e = 0; e < 4; ++e) acc[mt][nt][e] = 0.f;

    float4 ra0, ra1;
    auto lda_fetch = [&](int c) {
        if (arow_ok) {
            const float4* g = reinterpret_cast<const float4*>(gArow + (size_t)c * BK2);
            ra0 = __ldg(g);
            ra1 = __ldg(g + 1);
        } else {
            ra0 = make_float4(0.f, 0.f, 0.f, 0.f);
            ra1 = make_float4(0.f, 0.f, 0.f, 0.f);
        }
    };
    auto sts_a = [&](int c) {
        uint4 u;
        u.x = pack_h2(ra0.x, ra0.y);
        u.y = pack_h2(ra0.z, ra0.w);
        u.z = pack_h2(ra1.x, ra1.y);
        u.w = pack_h2(ra1.z, ra1.w);
        char* dst = sm2 + (c & (STAGES2 - 1)) * STAGE_BYTES2
                  + (size_t)arow * (PADA2 * 2) + aseg * 16;
        *reinterpret_cast<uint4*>(dst) = u;
    };
    auto issue_b = [&](int c) {
        const int s = c & (STAGES2 - 1);
        const uint32_t dbase = smem_u32(sm2 + s * STAGE_BYTES2) + A_BYTES2;
        const __half* gB = B16 + kStart + (size_t)c * BK2;
#pragma unroll
        for (int t = 0; t < 2; ++t) {
            const int idx = tid + t * 512;
            const int row = idx >> 2, seg = idx & 3;
            const uint32_t soff = (uint32_t)(row * PADB2 + seg * 8) * 2;
            cp_async16(dbase + soff, gB + (size_t)row * ldb + seg * 8);
        }
        cp_commit();
    };

    lda_fetch(0);
    for (int c = 0; c < STAGES2 - 1; ++c) issue_b(c);

    for (int c = 0; c < kChunks; ++c) {
        sts_a(c);
        cp_wait<STAGES2 - 2>();
        __syncthreads();
        if (c + 1 < kChunks) lda_fetch(c + 1);
        if (c + STAGES2 - 1 < kChunks) issue_b(c + STAGES2 - 1);
        else cp_commit();

        const char* stage = sm2 + (c & (STAGES2 - 1)) * STAGE_BYTES2;
        const uint32_t bA = smem_u32(stage) + aoff_lane;
        const uint32_t bB = smem_u32(stage + A_BYTES2) + boff_lane;

#pragma unroll
        for (int ks = 0; ks < BK2; ks += 16) {
            uint32_t af[2][4];
#pragma unroll
            for (int mt = 0; mt < 2; ++mt)
                ldmatrix_x4(af[mt][0], af[mt][1], af[mt][2], af[mt][3],
                            bA + (uint32_t)(mt * 16 * PADA2 * 2 + ks * 2));
            uint32_t bf[8][2];
#pragma unroll
            for (int i = 0; i < 4; ++i) {
                const uint32_t addr = bB + (uint32_t)(i * 16 * PADB2 * 2 + ks * 2);
                ldmatrix_x4(bf[2 * i][0], bf[2 * i][1],
                            bf[2 * i + 1][0], bf[2 * i + 1][1], addr);
            }
#pragma unroll
            for (int mt = 0; mt < 2; ++mt)
#pragma unroll
                for (int nt = 0; nt < 8; ++nt)
                    mma_fp16(acc[mt][nt], af[mt], bf[nt]);
        }
    }

    // ---- write own partial ----
#pragma unroll
    for (int mt = 0; mt < 2; ++mt) {
#pragma unroll
        for (int half = 0; half < 2; ++half) {
            const int r = m0 + wm + mt * 16 + l4 + half * 8;
            if (r >= M) continue;
#pragma unroll
            for (int nt = 0; nt < 8; ++nt) {
                const int cb = wn + nt * 8 + lm * 2;
                float2 v = make_float2(acc[mt][nt][half * 2], acc[mt][nt][half * 2 + 1]);
                *reinterpret_cast<float2*>(&Pp[(size_t)r * FF + cb]) = v;
            }
        }
    }

    // ---- split-K arrival; last block reduces all three slabs ----
    __threadfence();
    __syncthreads();
    __shared__ int s_last;
    if (tid == 0) {
        int* cnt = (MODE == 1 ? g_cnt1 : g_cnt3) + blockIdx.x;
        const int old = atomicAdd(cnt, 1);
        s_last = (old == SPLITK - 1);
        if (s_last) atomicExch(cnt, 0);   // self-reset for graph replay
    }
    __syncthreads();
    if (!s_last) return;
    __threadfence();

    const float alpha = (MODE == 1) ? __ldg(alphaPtr) : 0.f;
#pragma unroll
    for (int mt = 0; mt < 2; ++mt) {
#pragma unroll
        for (int half = 0; half < 2; ++half) {
            const int r = m0 + wm + mt * 16 + l4 + half * 8;
            if (r >= M) continue;
#pragma unroll
            for (int nt = 0; nt < 8; ++nt) {
                const int cb = wn + nt * 8 + lm * 2;
                const size_t off = (size_t)r * FF + cb;
                const float2 p0 = *reinterpret_cast<const float2*>(&P[off]);
                const float2 p1 = *reinterpret_cast<const float2*>(&P[(size_t)NN * FF + off]);
                const float2 p2 = *reinterpret_cast<const float2*>(&P[(size_t)2 * NN * FF + off]);
                if (MODE == 1) {
                    const float2 x = *reinterpret_cast<const float2*>(&inp[off]);
                    const float v0 = ((p0.x + p1.x) + p2.x) * INV_SCALE1 + alpha * x.x;
                    const float v1 = ((p0.y + p1.y) + p2.y) * INV_SCALE1 + alpha * x.y;
                    *reinterpret_cast<uint32_t*>(&g_support4h[off]) = pack_h2(v0, v1);
                } else {
                    float2 v;
                    v.x = (p0.x + p1.x) + p2.x;
                    v.y = (p0.y + p1.y) + p2.y;
                    *reinterpret_cast<float2*>(&outp[off]) = v;
                }
            }
        }
    }
}

// ========================================================================
// GEMM2: A = support4h (fp16, row-major), B = weightT16; both via cp.async.
// Epilogue writes supportT16 transposed fp16.
// ========================================================================
__global__ void __launch_bounds__(512, 1)
gemm2_a16(const __half* __restrict__ Ah,
          const __half* __restrict__ B16,
          int M) {
    extern __shared__ char sm2[];
    constexpr int kChunks = FF / BK2;   // 8

    const int tid  = threadIdx.x;
    const int wid  = tid >> 5;
    const int lane = tid & 31;
    const int l4   = lane >> 2;
    const int lm   = lane & 3;
    const int m0   = blockIdx.x * BM;
    const int wm   = (wid >> 2) * 32;
    const int wn   = (wid & 3) * 64;

    const int q = lane >> 3;
    const int rr = lane & 7;
    const uint32_t boff_lane =
        (uint32_t)((wn + (q >> 1) * 8 + rr) * PADB2 * 2 + (q & 1) * 16);
    const uint32_t aoff_lane =
        (uint32_t)((wm + (lane & 15)) * PADA2 * 2 + (lane >> 4) * 16);

    float acc[2][8][4];
#pragma unroll
    for (int mt = 0; mt < 2; ++mt)
#pragma unroll
        for (int nt = 0; nt < 8; ++nt)
#pragma unroll
            for (int e = 0; e < 4; ++e) acc[mt][nt][e] = 0.f;

    auto issue_ab = [&](int c) {
        const int s = c & (STAGES2 - 1);
        const uint32_t base = smem_u32(sm2 + s * STAGE_BYTES2);
        const __half* gA = Ah + (size_t)c * BK2;
        const __half* gB = B16 + (size_t)c * BK2;
#pragma unroll
        for (int t = 0; t < 3; ++t) {
            const int idx = tid + t * 512;     // 0..1535
            if (idx < 512) {                   // A: 128 rows x 4 segs (fp16)
                const int row = idx >> 2, seg = idx & 3;
                int grow = m0 + row;
                if (grow >= M) grow = m0;      // clamp (data masked in epilogue)
                cp_async16(base + (uint32_t)(row * PADA2 + seg * 8) * 2,
                           gA + (size_t)grow * FF + seg * 8);
            } else {                           // B: 256 rows x 4 segs (fp16)
                const int j = idx - 512;
                const int row = j >> 2, seg = j & 3;
                cp_async16(base + A_BYTES2 + (uint32_t)(row * PADB2 + seg * 8) * 2,
                           gB + (size_t)row * FF + seg * 8);
            }
        }
        cp_commit();
    };

    for (int c = 0; c < STAGES2 - 1; ++c) issue_ab(c);

    for (int c = 0; c < kChunks; ++c) {
        cp_wait<STAGES2 - 2>();
        __syncthreads();
        if (c + STAGES2 - 1 < kChunks) issue_ab(c + STAGES2 - 1);
        else cp_commit();

        const char* stage = sm2 + (c & (STAGES2 - 1)) * STAGE_BYTES2;
        const uint32_t bA = smem_u32(stage) + aoff_lane;
        const uint32_t bB = smem_u32(stage + A_BYTES2) + boff_lane;

#pragma unroll
        for (int ks = 0; ks < BK2; ks += 16) {
            uint32_t af[2][4];
#pragma unroll
            for (int mt = 0; mt < 2; ++mt)
                ldmatrix_x4(af[mt][0], af[mt][1], af[mt][2], af[mt][3],
                            bA + (uint32_t)(mt * 16 * PADA2 * 2 + ks * 2));
            uint32_t bf[8][2];
#pragma unroll
            for (int i = 0; i < 4; ++i) {
                const uint32_t addr = bB + (uint32_t)(i * 16 * PADB2 * 2 + ks * 2);
                ldmatrix_x4(bf[2 * i][0], bf[2 * i][1],
                            bf[2 * i + 1][0], bf[2 * i + 1][1], addr);
            }
#pragma unroll
            for (int mt = 0; mt < 2; ++mt)
#pragma unroll
                for (int nt = 0; nt < 8; ++nt)
                    mma_fp16(acc[mt][nt], af[mt], bf[nt]);
        }
    }

    // epilogue: supportT16[cb*NN + r] = fp16(acc)
#pragma unroll
    for (int mt = 0; mt < 2; ++mt) {
#pragma unroll
        for (int half = 0; half < 2; ++half) {
            const int r = m0 + wm + mt * 16 + l4 + half * 8;
            if (r >= M) continue;
#pragma unroll
            for (int nt = 0; nt < 8; ++nt) {
                const int cb = wn + nt * 8 + lm * 2;
                g_supportT16[(size_t)cb * NN + r] =
                    __float2half_rn(acc[mt][nt][half * 2]);
                g_supportT16[(size_t)(cb + 1) * NN + r] =
                    __float2half_rn(acc[mt][nt][half * 2 + 1]);
            }
        }
    }
}

// ========================================================================
// prologue kernels
// ========================================================================
__global__ void scores_kernel(const float* __restrict__ input,
                              const float* __restrict__ attn) {
    const int gw   = (blockIdx.x * blockDim.x + threadIdx.x) >> 5;
    const int lane = threadIdx.x & 31;
    if (gw >= NN) return;
    const float* row = input + (size_t)gw * FF;
    float s = 0.f;
#pragma unroll
    for (int j = 0; j < FF / 32; ++j)
        s += row[lane + 32 * j] * __ldg(&attn[lane + 32 * j]);
#pragma unroll
    for (int o = 16; o; o >>= 1) s += __shfl_xor_sync(0xFFFFFFFFu, s, o);
    if (lane == 0) g_scores[gw] = s;
}

__global__ void softmax_kernel() {
    const int tid = threadIdx.x, lane = tid & 31, warp = tid >> 5;
    __shared__ float red[32];
    __shared__ float s_max, s_sum;
    float m = -3.4e38f;
    for (int i = tid; i < NN; i += 1024) m = fmaxf(m, g_scores[i]);
#pragma unroll
    for (int o = 16; o; o >>= 1) m = fmaxf(m, __shfl_xor_sync(0xFFFFFFFFu, m, o));
    if (lane == 0) red[warp] = m;
    __syncthreads();
    if (warp == 0) {
        m = red[lane];
#pragma unroll
        for (int o = 16; o; o >>= 1) m = fmaxf(m, __shfl_xor_sync(0xFFFFFFFFu, m, o));
        if (lane == 0) s_max = m;
    }
    __syncthreads();
    const float mx = s_max;
    float s = 0.f;
    for (int i = tid; i < NN; i += 1024) s += expf(g_scores[i] - mx);
#pragma unroll
    for (int o = 16; o; o >>= 1) s += __shfl_xor_sync(0xFFFFFFFFu, s, o);
    if (lane == 0) red[warp] = s;
    __syncthreads();
    if (warp == 0) {
        s = red[lane];
#pragma unroll
        for (int o = 16; o; o >>= 1) s += __shfl_xor_sync(0xFFFFFFFFu, s, o);
        if (lane == 0) s_sum = s;
    }
    __syncthreads();
    const float inv = 1.0f / s_sum;
    for (int i = tid; i < NN; i += 1024) g_p[i] = expf(g_scores[i] - mx) * inv;
}

// merged: scaledT16 (blocks x<375) + weightT16 (blocks x>=375)
__global__ void prep_kernel(const float* __restrict__ input,
                            const float* __restrict__ weight) {
    __shared__ float t[32][33];
    const int tx = threadIdx.x, ty = threadIdx.y;
    if (blockIdx.x < NN / 32) {
        const int i0 = blockIdx.x * 32, f0 = blockIdx.y * 32;
        t[ty][tx] = g_p[i0 + ty] * SCALE1 * input[(size_t)(i0 + ty) * FF + f0 + tx];
        __syncthreads();
        g_scaledT16[(size_t)(f0 + ty) * NN + i0 + tx] = __float2half_rn(t[tx][ty]);
    } else {
        const int i0 = (blockIdx.x - NN / 32) * 32, o0 = blockIdx.y * 32;
        t[ty][tx] = weight[(size_t)(i0 + ty) * FF + o0 + tx];
        __syncthreads();
        g_weightT16[(size_t)(o0 + ty) * FF + i0 + tx] = __float2half_rn(t[tx][ty]);
    }
}

// ========================================================================
// launch
// ========================================================================
extern "C" void kernel_launch(void* const* d_in, const int* in_sizes, int n_in,
                              void* d_out, int out_size) {
    const float* input  = (const float*)d_in[0];
    const float* adj    = (const float*)d_in[1];
    const float* inc    = (const float*)d_in[2];
    const float* weight = (const float*)d_in[3];
    const float* attn   = (const float*)d_in[4];
    const float* alpha  = (const float*)d_in[5];
    float* out = (float*)d_out;

    cudaFuncSetAttribute(gemm_big<1>,
                         cudaFuncAttributeMaxDynamicSharedMemorySize, DYN_SMEM2);
    cudaFuncSetAttribute(gemm_big<3>,
                         cudaFuncAttributeMaxDynamicSharedMemorySize, DYN_SMEM2);
    cudaFuncSetAttribute(gemm2_a16,
                         cudaFuncAttributeMaxDynamicSharedMemorySize, DYN_SMEM2);

    __half *scaledT16, *supportT16, *weightT16, *support4h;
    float* part;
    cudaGetSymbolAddress((void**)&scaledT16,  g_scaledT16);
    cudaGetSymbolAddress((void**)&supportT16, g_supportT16);
    cudaGetSymbolAddress((void**)&weightT16,  g_weightT16);
    cudaGetSymbolAddress((void**)&support4h,  g_support4h);
    cudaGetSymbolAddress((void**)&part,       g_part);

    scores_kernel<<<(NN + 7) / 8, 256>>>(input, attn);
    softmax_kernel<<<1, 1024>>>();
    prep_kernel<<<dim3(NN / 32 + FF / 32, FF / 32), dim3(32, 32)>>>(input, weight);

    const int gridM = (NN + BM - 1) / BM;        // 94

    // GEMM1 (fp16, B x2^14) + fused reduce+alpha -> support4h (fp16)
    gemm_big<1><<<dim3(gridM, SPLITK), 512, DYN_SMEM2>>>(
        adj, NN, scaledT16, NN, NN, KCH_BIG2, part, input, alpha, nullptr);

    // GEMM2 (fp16 x fp16) -> supportT16 (transposed fp16)
    gemm2_a16<<<gridM, 512, DYN_SMEM2>>>(support4h, weightT16, NN);

    // GEMM3 (fp16) + fused final reduction -> out (fp32)
    gemm_big<3><<<dim3(gridM, SPLITK), 512, DYN_SMEM2>>>(
        inc, NN, supportT16, NN, NN, KCH_BIG2, part, nullptr, nullptr, out);

    (void)in_sizes; (void)n_in; (void)out_size;
}

// round 11
// speedup vs baseline: 1.0226x; 1.0226x over previous
#include <cuda_runtime.h>
#include <cuda_fp16.h>
#include <cstdint>
#include <math.h>

#define DEVFN static __device__ __forceinline__

// ---------------- problem constants ----------------
constexpr int NN  = 12000;
constexpr int NNK = 12032;               // K padded to multiple of 64
constexpr int FF  = 256;
constexpr float SCALE1     = 16384.f;
constexpr float INV_SCALE1 = 1.f / 16384.f;

// ---------------- big-GEMM config (BK=64) ----------------
constexpr int BM = 128;
constexpr int BN = 256;
constexpr int SPLITK = 3;
constexpr int BK3 = 64;
constexpr int PADA3 = 72;                          // halves per A row (144 B)
constexpr int PADB3 = 72;                          // halves per B row (144 B)
constexpr int A_BYTES3 = BM * PADA3 * 2;           // 18432
constexpr int B_BYTES3 = BN * PADB3 * 2;           // 36864
constexpr int STAGE_BYTES3 = A_BYTES3 + B_BYTES3;  // 55296
constexpr int DYN_SMEM3 = 3 * STAGE_BYTES3;        // 165888
constexpr int KCH_SLAB = 63;                       // slabs: 63,63,62 chunks

// ---------------- GEMM2 config (BK=32, from R9) ----------------
constexpr int BK2 = 32;
constexpr int STAGES2 = 4;
constexpr int PADA2 = 40;
constexpr int PADB2 = 40;
constexpr int A_BYTES2 = BM * PADA2 * 2;           // 10240
constexpr int B_BYTES2 = BN * PADB2 * 2;           // 20480
constexpr int STAGE_BYTES2 = A_BYTES2 + B_BYTES2;  // 30720
constexpr int DYN_SMEM2 = STAGES2 * STAGE_BYTES2;  // 122880

// ---------------- device scratch -------------------
__device__ float g_scores[NN];
__device__ float g_p[NN];
__device__ __half g_scaledT16[(size_t)FF * NNK];   // B for GEMM1 (fp16, x2^14)
__device__ __half g_supportT16[(size_t)FF * NNK];  // B for GEMM3 (fp16)
__device__ __half g_weightT16[FF * FF];            // B for GEMM2 (fp16)
__device__ float g_part[(size_t)SPLITK * NN * FF]; // split-K partials

// ---------------- PTX helpers ----------------------
DEVFN uint32_t smem_u32(const void* p) {
    uint32_t a;
    asm("{ .reg .u64 t; cvta.to.shared.u64 t, %1; cvt.u32.u64 %0, t; }" : "=r"(a) : "l"(p));
    return a;
}
DEVFN void cp_async16(uint32_t saddr, const void* gaddr) {
    asm volatile("cp.async.cg.shared.global [%0], [%1], 16;"
                 :: "r"(saddr), "l"(gaddr) : "memory");
}
DEVFN void cp_commit() { asm volatile("cp.async.commit_group;" ::: "memory"); }
template <int N> DEVFN void cp_wait() { asm volatile("cp.async.wait_group %0;" :: "n"(N) : "memory"); }

DEVFN void ldmatrix_x4(uint32_t& r0, uint32_t& r1, uint32_t& r2, uint32_t& r3,
                       uint32_t addr) {
    asm volatile("ldmatrix.sync.aligned.m8n8.x4.shared.b16 {%0,%1,%2,%3}, [%4];"
                 : "=r"(r0), "=r"(r1), "=r"(r2), "=r"(r3) : "r"(addr));
}
DEVFN uint32_t pack_h2(float lo, float hi) {
    __half2 h = __float22half2_rn(make_float2(lo, hi));
    return *reinterpret_cast<uint32_t*>(&h);
}
DEVFN void mma_fp16(float* c, const uint32_t* a, const uint32_t* b) {
    asm volatile(
        "mma.sync.aligned.m16n8k16.row.col.f32.f16.f16.f32 "
        "{%0,%1,%2,%3}, {%4,%5,%6,%7}, {%8,%9}, {%0,%1,%2,%3};"
        : "+f"(c[0]), "+f"(c[1]), "+f"(c[2]), "+f"(c[3])
        : "r"(a[0]), "r"(a[1]), "r"(a[2]), "r"(a[3]), "r"(b[0]), "r"(b[1]));
}

// ========================================================================
// Big GEMM partial (BK=64): P[r,c] = fp16(A[r, kSlab]) @ B16[c, kSlab]^T
//   B16 has NNK columns with zeroed pad; A K-pad reads clamped in-bounds.
// ========================================================================
__global__ void __launch_bounds__(512, 1)
gemm_h16(const float* __restrict__ A, int lda,
         const __half* __restrict__ B16,
         int M, float* __restrict__ P) {
    extern __shared__ char sm2[];

    const int tid  = threadIdx.x;
    const int wid  = tid >> 5;
    const int lane = tid & 31;
    const int l4   = lane >> 2;
    const int lm   = lane & 3;
    const int m0   = blockIdx.x * BM;
    const int wm   = (wid >> 2) * 32;
    const int wn   = (wid & 3) * 64;
    const int slab = blockIdx.y;
    const int kChunks = (slab == SPLITK - 1) ? 62 : 63;
    const int kStart  = slab * KCH_SLAB * BK3;      // 0, 4032, 8064
    float* __restrict__ Pp = P + (size_t)slab * NN * FF;

    const int q = lane >> 3;
    const int rr = lane & 7;
    const uint32_t boff_lane =
        (uint32_t)((wn + (q >> 1) * 8 + rr) * PADB3 * 2 + (q & 1) * 16);
    const uint32_t aoff_lane =
        (uint32_t)((wm + (lane & 15)) * PADA3 * 2 + (lane >> 4) * 16);

    // A loader: 128 rows x 4 groups of 16 fp32
    const int arow = tid >> 2;
    const int aseg = tid & 3;
    const bool arow_ok = (m0 + arow) < M;
    const float* gA = A + (size_t)(m0 + arow) * lda;

    float acc[2][8][4];
#pragma unroll
    for (int mt = 0; mt < 2; ++mt)
#pragma unroll
        for (int nt = 0; nt < 8; ++nt)
#pragma unroll
            for (int e = 0; e < 4; ++e) acc[mt][nt][e] = 0.f;

    float4 ra[4];
    auto lda_fetch = [&](int c) {
        if (arow_ok) {
            int o = kStart + c * BK3 + aseg * 16;
            if (o + 16 > NN) o = 0;   // K-pad clamp; B pad zeros nullify
            const float4* g = reinterpret_cast<const float4*>(gA + o);
            ra[0] = __ldg(g);
            ra[1] = __ldg(g + 1);
            ra[2] = __ldg(g + 2);
            ra[3] = __ldg(g + 3);
        } else {
            ra[0] = ra[1] = ra[2] = ra[3] = make_float4(0.f, 0.f, 0.f, 0.f);
        }
    };
    auto sts_a = [&](int c) {
        uint4 u0, u1;
        u0.x = pack_h2(ra[0].x, ra[0].y); u0.y = pack_h2(ra[0].z, ra[0].w);
        u0.z = pack_h2(ra[1].x, ra[1].y); u0.w = pack_h2(ra[1].z, ra[1].w);
        u1.x = pack_h2(ra[2].x, ra[2].y); u1.y = pack_h2(ra[2].z, ra[2].w);
        u1.z = pack_h2(ra[3].x, ra[3].y); u1.w = pack_h2(ra[3].z, ra[3].w);
        char* dst = sm2 + (c % 3) * STAGE_BYTES3
                  + (size_t)arow * (PADA3 * 2) + aseg * 32;
        reinterpret_cast<uint4*>(dst)[0] = u0;
        reinterpret_cast<uint4*>(dst)[1] = u1;
    };
    auto issue_b = [&](int c) {
        const uint32_t dbase = smem_u32(sm2 + (c % 3) * STAGE_BYTES3) + A_BYTES3;
        const __half* gB = B16 + kStart + (size_t)c * BK3;
#pragma unroll
        for (int t = 0; t < 4; ++t) {
            const int idx = tid + t * 512;       // 2048 segs: 256 rows x 8
            const int row = idx >> 3, seg = idx & 7;
            cp_async16(dbase + (uint32_t)(row * PADB3 + seg * 8) * 2,
                       gB + (size_t)row * NNK + seg * 8);
        }
        cp_commit();
    };

    lda_fetch(0);
    issue_b(0);
    issue_b(1);

    for (int c = 0; c < kChunks; ++c) {
        sts_a(c);
        cp_wait<1>();
        __syncthreads();
        if (c + 1 < kChunks) lda_fetch(c + 1);
        if (c + 2 < kChunks) issue_b(c + 2);
        else cp_commit();

        const char* stage = sm2 + (c % 3) * STAGE_BYTES3;
        const uint32_t bA = smem_u32(stage) + aoff_lane;
        const uint32_t bB = smem_u32(stage + A_BYTES3) + boff_lane;

#pragma unroll
        for (int ks = 0; ks < BK3; ks += 16) {
            uint32_t af[2][4];
#pragma unroll
            for (int mt = 0; mt < 2; ++mt)
                ldmatrix_x4(af[mt][0], af[mt][1], af[mt][2], af[mt][3],
                            bA + (uint32_t)(mt * 16 * PADA3 * 2 + ks * 2));
            uint32_t bf[8][2];
#pragma unroll
            for (int i = 0; i < 4; ++i) {
                const uint32_t addr = bB + (uint32_t)(i * 16 * PADB3 * 2 + ks * 2);
                ldmatrix_x4(bf[2 * i][0], bf[2 * i][1],
                            bf[2 * i + 1][0], bf[2 * i + 1][1], addr);
            }
#pragma unroll
            for (int mt = 0; mt < 2; ++mt)
#pragma unroll
                for (int nt = 0; nt < 8; ++nt)
                    mma_fp16(acc[mt][nt], af[mt], bf[nt]);
        }
    }

#pragma unroll
    for (int mt = 0; mt < 2; ++mt) {
#pragma unroll
        for (int half = 0; half < 2; ++half) {
            const int r = m0 + wm + mt * 16 + l4 + half * 8;
            if (r >= M) continue;
#pragma unroll
            for (int nt = 0; nt < 8; ++nt) {
                const int cb = wn + nt * 8 + lm * 2;
                float2 v = make_float2(acc[mt][nt][half * 2], acc[mt][nt][half * 2 + 1]);
                *reinterpret_cast<float2*>(&Pp[(size_t)r * FF + cb]) = v;
            }
        }
    }
}

// ========================================================================
// GEMM2 fused (R9): A = sum(partials)*2^-14 + alpha*input in the loader,
//   B = weightT16; epilogue writes supportT16 transposed fp16 (stride NNK).
// ========================================================================
__global__ void __launch_bounds__(512, 1)
gemm2_fused(const float* __restrict__ inp,
            const float* __restrict__ alphaPtr,
            const __half* __restrict__ B16,
            int M) {
    extern __shared__ char sm2[];
    constexpr int kChunks = FF / BK2;   // 8

    const int tid  = threadIdx.x;
    const int wid  = tid >> 5;
    const int lane = tid & 31;
    const int l4   = lane >> 2;
    const int lm   = lane & 3;
    const int m0   = blockIdx.x * BM;
    const int wm   = (wid >> 2) * 32;
    const int wn   = (wid & 3) * 64;
    const float alpha = __ldg(alphaPtr);

    const int q = lane >> 3;
    const int rr = lane & 7;
    const uint32_t boff_lane =
        (uint32_t)((wn + (q >> 1) * 8 + rr) * PADB2 * 2 + (q & 1) * 16);
    const uint32_t aoff_lane =
        (uint32_t)((wm + (lane & 15)) * PADA2 * 2 + (lane >> 4) * 16);

    const int arow = tid >> 2;
    const int aseg = tid & 3;
    const bool arow_ok = (m0 + arow) < M;
    const size_t abase = (size_t)(m0 + arow) * FF + aseg * 8;

    float acc[2][8][4];
#pragma unroll
    for (int mt = 0; mt < 2; ++mt)
#pragma unroll
        for (int nt = 0; nt < 8; ++nt)
#pragma unroll
            for (int e = 0; e < 4; ++e) acc[mt][nt][e] = 0.f;

    float4 ra0, ra1;
    auto lda_fetch = [&](int c) {
        if (arow_ok) {
            const size_t off = abase + (size_t)c * BK2;
            const float4* g0 = reinterpret_cast<const float4*>(&g_part[off]);
            const float4* g1 = reinterpret_cast<const float4*>(&g_part[(size_t)NN * FF + off]);
            const float4* g2 = reinterpret_cast<const float4*>(&g_part[(size_t)2 * NN * FF + off]);
            const float4* gx = reinterpret_cast<const float4*>(&inp[off]);
            float4 p0 = __ldg(g0), p1 = __ldg(g1), p2 = __ldg(g2), x = __ldg(gx);
            ra0.x = (p0.x + p1.x + p2.x) * INV_SCALE1 + alpha * x.x;
            ra0.y = (p0.y + p1.y + p2.y) * INV_SCALE1 + alpha * x.y;
            ra0.z = (p0.z + p1.z + p2.z) * INV_SCALE1 + alpha * x.z;
            ra0.w = (p0.w + p1.w + p2.w) * INV_SCALE1 + alpha * x.w;
            p0 = __ldg(g0 + 1); p1 = __ldg(g1 + 1); p2 = __ldg(g2 + 1); x = __ldg(gx + 1);
            ra1.x = (p0.x + p1.x + p2.x) * INV_SCALE1 + alpha * x.x;
            ra1.y = (p0.y + p1.y + p2.y) * INV_SCALE1 + alpha * x.y;
            ra1.z = (p0.z + p1.z + p2.z) * INV_SCALE1 + alpha * x.z;
            ra1.w = (p0.w + p1.w + p2.w) * INV_SCALE1 + alpha * x.w;
        } else {
            ra0 = make_float4(0.f, 0.f, 0.f, 0.f);
            ra1 = make_float4(0.f, 0.f, 0.f, 0.f);
        }
    };
    auto sts_a = [&](int c) {
        uint4 u;
        u.x = pack_h2(ra0.x, ra0.y);
        u.y = pack_h2(ra0.z, ra0.w);
        u.z = pack_h2(ra1.x, ra1.y);
        u.w = pack_h2(ra1.z, ra1.w);
        char* dst = sm2 + (c & (STAGES2 - 1)) * STAGE_BYTES2
                  + (size_t)arow * (PADA2 * 2) + aseg * 16;
        *reinterpret_cast<uint4*>(dst) = u;
    };
    auto issue_b = [&](int c) {
        const int s = c & (STAGES2 - 1);
        const uint32_t dbase = smem_u32(sm2 + s * STAGE_BYTES2) + A_BYTES2;
        const __half* gB = B16 + (size_t)c * BK2;
#pragma unroll
        for (int t = 0; t < 2; ++t) {
            const int idx = tid + t * 512;
            const int row = idx >> 2, seg = idx & 3;
            const uint32_t soff = (uint32_t)(row * PADB2 + seg * 8) * 2;
            cp_async16(dbase + soff, gB + (size_t)row * FF + seg * 8);
        }
        cp_commit();
    };

    lda_fetch(0);
    for (int c = 0; c < STAGES2 - 1; ++c) issue_b(c);

    for (int c = 0; c < kChunks; ++c) {
        sts_a(c);
        cp_wait<STAGES2 - 2>();
        __syncthreads();
        if (c + 1 < kChunks) lda_fetch(c + 1);
        if (c + STAGES2 - 1 < kChunks) issue_b(c + STAGES2 - 1);
        else cp_commit();

        const char* stage = sm2 + (c & (STAGES2 - 1)) * STAGE_BYTES2;
        const uint32_t bA = smem_u32(stage) + aoff_lane;
        const uint32_t bB = smem_u32(stage + A_BYTES2) + boff_lane;

#pragma unroll
        for (int ks = 0; ks < BK2; ks += 16) {
            uint32_t af[2][4];
#pragma unroll
            for (int mt = 0; mt < 2; ++mt)
                ldmatrix_x4(af[mt][0], af[mt][1], af[mt][2], af[mt][3],
                            bA + (uint32_t)(mt * 16 * PADA2 * 2 + ks * 2));
            uint32_t bf[8][2];
#pragma unroll
            for (int i = 0; i < 4; ++i) {
                const uint32_t addr = bB + (uint32_t)(i * 16 * PADB2 * 2 + ks * 2);
                ldmatrix_x4(bf[2 * i][0], bf[2 * i][1],
                            bf[2 * i + 1][0], bf[2 * i + 1][1], addr);
            }
#pragma unroll
            for (int mt = 0; mt < 2; ++mt)
#pragma unroll
                for (int nt = 0; nt < 8; ++nt)
                    mma_fp16(acc[mt][nt], af[mt], bf[nt]);
        }
    }

    // epilogue: supportT16[cb*NNK + r] = fp16(acc)
#pragma unroll
    for (int mt = 0; mt < 2; ++mt) {
#pragma unroll
        for (int half = 0; half < 2; ++half) {
            const int r = m0 + wm + mt * 16 + l4 + half * 8;
            if (r >= M) continue;
#pragma unroll
            for (int nt = 0; nt < 8; ++nt) {
                const int cb = wn + nt * 8 + lm * 2;
                g_supportT16[(size_t)cb * NNK + r] =
                    __float2half_rn(acc[mt][nt][half * 2]);
                g_supportT16[(size_t)(cb + 1) * NNK + r] =
                    __float2half_rn(acc[mt][nt][half * 2 + 1]);
            }
        }
    }
}

// ========================================================================
// reduction / prologue kernels
// ========================================================================
__global__ void reduce_sum_kernel(float* __restrict__ out) {
    const size_t i = ((size_t)blockIdx.x * blockDim.x + threadIdx.x) * 4;
    float4 p0 = *reinterpret_cast<const float4*>(&g_part[i]);
    float4 p1 = *reinterpret_cast<const float4*>(&g_part[(size_t)NN * FF + i]);
    float4 p2 = *reinterpret_cast<const float4*>(&g_part[(size_t)2 * NN * FF + i]);
    float4 r;
    r.x = p0.x + p1.x + p2.x;
    r.y = p0.y + p1.y + p2.y;
    r.z = p0.z + p1.z + p2.z;
    r.w = p0.w + p1.w + p2.w;
    *reinterpret_cast<float4*>(&out[i]) = r;
}

// zero the K-pad columns of scaledT16 / supportT16
__global__ void zeropad_kernel() {
    const int t = blockIdx.x * blockDim.x + threadIdx.x;   // 0..8191
    if (t < FF * (NNK - NN)) {
        const int f = t >> 5, c = t & 31;
        g_scaledT16[(size_t)f * NNK + NN + c]  = __float2half(0.f);
        g_supportT16[(size_t)f * NNK + NN + c] = __float2half(0.f);
    }
}

__global__ void scores_kernel(const float* __restrict__ input,
                              const float* __restrict__ attn) {
    const int gw   = (blockIdx.x * blockDim.x + threadIdx.x) >> 5;
    const int lane = threadIdx.x & 31;
    if (gw >= NN) return;
    const float* row = input + (size_t)gw * FF;
    float s = 0.f;
#pragma unroll
    for (int j = 0; j < FF / 32; ++j)
        s += row[lane + 32 * j] * __ldg(&attn[lane + 32 * j]);
#pragma unroll
    for (int o = 16; o; o >>= 1) s += __shfl_xor_sync(0xFFFFFFFFu, s, o);
    if (lane == 0) g_scores[gw] = s;
}

__global__ void softmax_kernel() {
    const int tid = threadIdx.x, lane = tid & 31, warp = tid >> 5;
    __shared__ float red[32];
    __shared__ float s_max, s_sum;
    float m = -3.4e38f;
    for (int i = tid; i < NN; i += 1024) m = fmaxf(m, g_scores[i]);
#pragma unroll
    for (int o = 16; o; o >>= 1) m = fmaxf(m, __shfl_xor_sync(0xFFFFFFFFu, m, o));
    if (lane == 0) red[warp] = m;
    __syncthreads();
    if (warp == 0) {
        m = red[lane];
#pragma unroll
        for (int o = 16; o; o >>= 1) m = fmaxf(m, __shfl_xor_sync(0xFFFFFFFFu, m, o));
        if (lane == 0) s_max = m;
    }
    __syncthreads();
    const float mx = s_max;
    float s = 0.f;
    for (int i = tid; i < NN; i += 1024) s += expf(g_scores[i] - mx);
#pragma unroll
    for (int o = 16; o; o >>= 1) s += __shfl_xor_sync(0xFFFFFFFFu, s, o);
    if (lane == 0) red[warp] = s;
    __syncthreads();
    if (warp == 0) {
        s = red[lane];
#pragma unroll
        for (int o = 16; o; o >>= 1) s += __shfl_xor_sync(0xFFFFFFFFu, s, o);
        if (lane == 0) s_sum = s;
    }
    __syncthreads();
    const float inv = 1.0f / s_sum;
    for (int i = tid; i < NN; i += 1024) g_p[i] = expf(g_scores[i] - mx) * inv;
}

// merged prep: scaledT16 (x<375, stride NNK) + weightT16 (x>=375)
__global__ void prep_kernel(const float* __restrict__ input,
                            const float* __restrict__ weight) {
    __shared__ float t[32][33];
    const int tx = threadIdx.x, ty = threadIdx.y;
    if (blockIdx.x < NN / 32) {
        const int i0 = blockIdx.x * 32, f0 = blockIdx.y * 32;
        t[ty][tx] = g_p[i0 + ty] * SCALE1 * input[(size_t)(i0 + ty) * FF + f0 + tx];
        __syncthreads();
        g_scaledT16[(size_t)(f0 + ty) * NNK + i0 + tx] = __float2half_rn(t[tx][ty]);
    } else {
        const int i0 = (blockIdx.x - NN / 32) * 32, o0 = blockIdx.y * 32;
        t[ty][tx] = weight[(size_t)(i0 + ty) * FF + o0 + tx];
        __syncthreads();
        g_weightT16[(size_t)(o0 + ty) * FF + i0 + tx] = __float2half_rn(t[tx][ty]);
    }
}

// ========================================================================
// launch
// ========================================================================
extern "C" void kernel_launch(void* const* d_in, const int* in_sizes, int n_in,
                              void* d_out, int out_size) {
    const float* input  = (const float*)d_in[0];
    const float* adj    = (const float*)d_in[1];
    const float* inc    = (const float*)d_in[2];
    const float* weight = (const float*)d_in[3];
    const float* attn   = (const float*)d_in[4];
    const float* alpha  = (const float*)d_in[5];
    float* out = (float*)d_out;

    cudaFuncSetAttribute(gemm_h16,
                         cudaFuncAttributeMaxDynamicSharedMemorySize, DYN_SMEM3);
    cudaFuncSetAttribute(gemm2_fused,
                         cudaFuncAttributeMaxDynamicSharedMemorySize, DYN_SMEM2);

    __half *scaledT16, *supportT16, *weightT16;
    float* part;
    cudaGetSymbolAddress((void**)&scaledT16,  g_scaledT16);
    cudaGetSymbolAddress((void**)&supportT16, g_supportT16);
    cudaGetSymbolAddress((void**)&weightT16,  g_weightT16);
    cudaGetSymbolAddress((void**)&part,       g_part);

    zeropad_kernel<<<32, 256>>>();
    scores_kernel<<<(NN + 7) / 8, 256>>>(input, attn);
    softmax_kernel<<<1, 1024>>>();
    prep_kernel<<<dim3(NN / 32 + FF / 32, FF / 32), dim3(32, 32)>>>(input, weight);

    const int gridM = (NN + BM - 1) / BM;        // 94
    const int redBlocks = (NN * FF / 4) / 1024;  // 750

    // GEMM1 (fp16, B x2^14, BK=64): partials of adj @ scaled
    gemm_h16<<<dim3(gridM, SPLITK), 512, DYN_SMEM3>>>(adj, NN, scaledT16, NN, part);

    // GEMM2 fused: A = sum(part)*2^-14 + alpha*input; writes supportT16^T
    gemm2_fused<<<gridM, 512, DYN_SMEM2>>>(input, alpha, weightT16, NN);

    // GEMM3 (fp16, BK=64): partials of incidence @ support
    gemm_h16<<<dim3(gridM, SPLITK), 512, DYN_SMEM3>>>(inc, NN, supportT16, NN, part);
    reduce_sum_kernel<<<redBlocks, 1024>>>(out);

    (void)in_sizes; (void)n_in; (void)out_size;
}